// round 6
// baseline (speedup 1.0000x reference)
#include <cuda_runtime.h>
#include <cstdint>

// FlashAttention via 3xTF32 mma.sync, 8-warp N-split.
// All hi/lo splits hoisted out of the hot loop:
//   - K,V pre-split in GMEM by a prep kernel (device-global buffers)
//   - Q pre-split once per CTA into smem
//   - only P is split per-iteration (16 splits/warp-iter)
// N=8192, D=128, no softmax scaling. sm_103a.

#define NSEQ 8192
#define DIM 128
#define BM 64
#define BN 64
#define SQK 132   // Q,K stride: 132 % 32 == 4 -> (4g+tig) banks conflict-free
#define SVS 136   // V stride:   136 % 32 == 8 -> (8tig+g) banks conflict-free
#define SPS 68    //  68 % 32 == 4 -> conflict-free, P has only 64 cols

// SQh,SQl,SKh,SKl: 4*64*132; SVh,SVl: 2*64*136; SP: 64*68; stats: 256
#define SMEM_FLOATS (4*BM*SQK + 2*BN*SVS + BM*SPS + 256)

__device__ float g_kh[NSEQ * DIM];
__device__ float g_kl[NSEQ * DIM];
__device__ float g_vh[NSEQ * DIM];
__device__ float g_vl[NSEQ * DIM];

__device__ __forceinline__ uint32_t f2tf(float x) {
    uint32_t r;
    asm("cvt.rna.tf32.f32 %0, %1;" : "=r"(r) : "f"(x));
    return r;
}
__device__ __forceinline__ void tf_split(float x, uint32_t& hi, uint32_t& lo) {
    hi = f2tf(x);
    lo = f2tf(x - __uint_as_float(hi));
}
__device__ __forceinline__ void split1(float x, float& h, float& l) {
    h = __uint_as_float(f2tf(x));
    l = __uint_as_float(f2tf(x - h));
}
__device__ __forceinline__ void mma_tf32(float* c, const uint32_t* a,
                                         uint32_t b0, uint32_t b1) {
    asm volatile(
        "mma.sync.aligned.m16n8k8.row.col.f32.tf32.tf32.f32 "
        "{%0,%1,%2,%3}, {%4,%5,%6,%7}, {%8,%9}, {%0,%1,%2,%3};"
        : "+f"(c[0]), "+f"(c[1]), "+f"(c[2]), "+f"(c[3])
        : "r"(a[0]), "r"(a[1]), "r"(a[2]), "r"(a[3]), "r"(b0), "r"(b1));
}

// ---- prep: split K,V into tf32 hi/lo streams in GMEM ----
__global__ __launch_bounds__(256)
void split_kv_kernel(const float* __restrict__ k, const float* __restrict__ v) {
    int i = blockIdx.x * 256 + threadIdx.x;     // float4 index, 262144 total
    float4 kx = ((const float4*)k)[i];
    float4 vx = ((const float4*)v)[i];
    float4 kh, kl, vh, vl;
    split1(kx.x, kh.x, kl.x); split1(kx.y, kh.y, kl.y);
    split1(kx.z, kh.z, kl.z); split1(kx.w, kh.w, kl.w);
    split1(vx.x, vh.x, vl.x); split1(vx.y, vh.y, vl.y);
    split1(vx.z, vh.z, vl.z); split1(vx.w, vh.w, vl.w);
    ((float4*)g_kh)[i] = kh; ((float4*)g_kl)[i] = kl;
    ((float4*)g_vh)[i] = vh; ((float4*)g_vl)[i] = vl;
}

__global__ __launch_bounds__(256, 1)
void fa_tf32_kernel(const float* __restrict__ q,
                    float* __restrict__ out) {
    extern __shared__ float sm[];
    float* SQh = sm;                      // 64 x 132
    float* SQl = SQh + BM * SQK;
    float* SKh = SQl + BM * SQK;
    float* SKl = SKh + BN * SQK;
    float* SVh = SKl + BN * SQK;          // 64 x 136
    float* SVl = SVh + BN * SVS;
    float* SP  = SVl + BN * SVS;          // 64 x 68
    float* SMx = SP  + BM * SPS;          // 2 x 64
    float* SSm = SMx + 128;               // 2 x 64

    const int tid  = threadIdx.x;
    const int warp = tid >> 5;
    const int lane = tid & 31;
    const int g    = lane >> 2;
    const int tig  = lane & 3;
    const int rg   = warp & 3;     // row group
    const int h    = warp >> 2;    // key half
    const int wr   = rg * 16;
    const int qrow0 = blockIdx.x * BM;

    // ---- load + split Q tile once ----
    {
        const float4* qg = (const float4*)(q + (size_t)qrow0 * DIM);
        #pragma unroll
        for (int t = 0; t < 8; t++) {
            int i = tid + 256 * t;       // 2048 float4
            int row = i >> 5;
            int dd = (i & 31) << 2;
            float4 qx = qg[i];
            float4 qh, ql;
            split1(qx.x, qh.x, ql.x); split1(qx.y, qh.y, ql.y);
            split1(qx.z, qh.z, ql.z); split1(qx.w, qh.w, ql.w);
            *(float4*)(SQh + row * SQK + dd) = qh;
            *(float4*)(SQl + row * SQK + dd) = ql;
        }
    }

    float o[16][4];
    #pragma unroll
    for (int nt = 0; nt < 16; nt++)
        #pragma unroll
        for (int i = 0; i < 4; i++) o[nt][i] = 0.0f;
    float m0 = -1e30f, m1 = -1e30f, l0 = 0.0f, l1 = 0.0f;

    const float* Sqh0 = SQh + (wr + g) * SQK;
    const float* Sqh1 = Sqh0 + 8 * SQK;
    const float* Sql0 = SQl + (wr + g) * SQK;
    const float* Sql1 = Sql0 + 8 * SQK;
    float* Sp0 = SP + (wr + g) * SPS;
    float* Sp1 = Sp0 + 8 * SPS;

    #pragma unroll 1
    for (int kb = 0; kb < NSEQ / BN; kb++) {
        __syncthreads();   // prior iter's smem reads complete (covers Q split too)

        // ---- stream pre-split K,V tiles (pure copy, no ALU) ----
        {
            const size_t base = (size_t)kb * BN * DIM / 4;
            #pragma unroll
            for (int t = 0; t < 8; t++) {
                int i = tid + 256 * t;
                int row = i >> 5;
                int dd = (i & 31) << 2;
                *(float4*)(SKh + row * SQK + dd) = ((const float4*)g_kh)[base + i];
                *(float4*)(SKl + row * SQK + dd) = ((const float4*)g_kl)[base + i];
                *(float4*)(SVh + row * SVS + dd) = ((const float4*)g_vh)[base + i];
                *(float4*)(SVl + row * SVS + dd) = ((const float4*)g_vl)[base + i];
            }
        }
        __syncthreads();

        // ---- S = Q K^T over this warp's key half (4 n-tiles) ----
        float s[4][4];
        #pragma unroll
        for (int nt = 0; nt < 4; nt++)
            #pragma unroll
            for (int i = 0; i < 4; i++) s[nt][i] = 0.0f;

        #pragma unroll 4
        for (int kc = 0; kc < DIM / 8; kc++) {
            uint32_t ah[4], al[4];
            ah[0] = __float_as_uint(Sqh0[8 * kc + tig]);
            ah[1] = __float_as_uint(Sqh1[8 * kc + tig]);
            ah[2] = __float_as_uint(Sqh0[8 * kc + tig + 4]);
            ah[3] = __float_as_uint(Sqh1[8 * kc + tig + 4]);
            al[0] = __float_as_uint(Sql0[8 * kc + tig]);
            al[1] = __float_as_uint(Sql1[8 * kc + tig]);
            al[2] = __float_as_uint(Sql0[8 * kc + tig + 4]);
            al[3] = __float_as_uint(Sql1[8 * kc + tig + 4]);
            #pragma unroll
            for (int nt = 0; nt < 4; nt++) {
                int ntg = h * 4 + nt;
                const float* kph = SKh + (ntg * 8 + g) * SQK + 8 * kc + tig;
                const float* kpl = SKl + (ntg * 8 + g) * SQK + 8 * kc + tig;
                uint32_t bh0 = __float_as_uint(kph[0]);
                uint32_t bh1 = __float_as_uint(kph[4]);
                uint32_t bl0 = __float_as_uint(kpl[0]);
                uint32_t bl1 = __float_as_uint(kpl[4]);
                mma_tf32(s[nt], ah, bh0, bh1);
                mma_tf32(s[nt], ah, bl0, bl1);
                mma_tf32(s[nt], al, bh0, bh1);
            }
        }

        // ---- softmax: cross-half stat exchange ----
        float mx0 = -1e30f, mx1 = -1e30f;
        #pragma unroll
        for (int nt = 0; nt < 4; nt++) {
            mx0 = fmaxf(mx0, fmaxf(s[nt][0], s[nt][1]));
            mx1 = fmaxf(mx1, fmaxf(s[nt][2], s[nt][3]));
        }
        mx0 = fmaxf(mx0, __shfl_xor_sync(0xffffffffu, mx0, 1));
        mx0 = fmaxf(mx0, __shfl_xor_sync(0xffffffffu, mx0, 2));
        mx1 = fmaxf(mx1, __shfl_xor_sync(0xffffffffu, mx1, 1));
        mx1 = fmaxf(mx1, __shfl_xor_sync(0xffffffffu, mx1, 2));
        if (tig == 0) {
            SMx[h * 64 + wr + g]     = mx0;
            SMx[h * 64 + wr + 8 + g] = mx1;
        }
        __syncthreads();
        mx0 = fmaxf(mx0, SMx[(1 - h) * 64 + wr + g]);
        mx1 = fmaxf(mx1, SMx[(1 - h) * 64 + wr + 8 + g]);

        float mn0 = fmaxf(m0, mx0), mn1 = fmaxf(m1, mx1);
        float alpha0 = __expf(m0 - mn0), alpha1 = __expf(m1 - mn1);
        m0 = mn0; m1 = mn1;

        float sum0 = 0.0f, sum1 = 0.0f;
        #pragma unroll
        for (int nt = 0; nt < 4; nt++) {
            s[nt][0] = __expf(s[nt][0] - mn0);
            s[nt][1] = __expf(s[nt][1] - mn0);
            s[nt][2] = __expf(s[nt][2] - mn1);
            s[nt][3] = __expf(s[nt][3] - mn1);
            sum0 += s[nt][0] + s[nt][1];
            sum1 += s[nt][2] + s[nt][3];
        }
        sum0 += __shfl_xor_sync(0xffffffffu, sum0, 1);
        sum0 += __shfl_xor_sync(0xffffffffu, sum0, 2);
        sum1 += __shfl_xor_sync(0xffffffffu, sum1, 1);
        sum1 += __shfl_xor_sync(0xffffffffu, sum1, 2);
        if (tig == 0) {
            SSm[h * 64 + wr + g]     = sum0;
            SSm[h * 64 + wr + 8 + g] = sum1;
        }
        // write P (own rows, own key-half columns)
        #pragma unroll
        for (int nt = 0; nt < 4; nt++) {
            int ntg = h * 4 + nt;
            *(float2*)(Sp0 + ntg * 8 + 2 * tig) = make_float2(s[nt][0], s[nt][1]);
            *(float2*)(Sp1 + ntg * 8 + 2 * tig) = make_float2(s[nt][2], s[nt][3]);
        }
        __syncthreads();
        sum0 += SSm[(1 - h) * 64 + wr + g];
        sum1 += SSm[(1 - h) * 64 + wr + 8 + g];
        l0 = l0 * alpha0 + sum0;
        l1 = l1 * alpha1 + sum1;

        #pragma unroll
        for (int nt = 0; nt < 16; nt++) {
            o[nt][0] *= alpha0; o[nt][1] *= alpha0;
            o[nt][2] *= alpha1; o[nt][3] *= alpha1;
        }

        // ---- O += P V over this warp's j-half (only P split here) ----
        #pragma unroll 2
        for (int kcl = 0; kcl < 4; kcl++) {
            int kcg = h * 4 + kcl;
            uint32_t ah[4], al[4];
            tf_split(Sp0[8 * kcg + tig],     ah[0], al[0]);
            tf_split(Sp1[8 * kcg + tig],     ah[1], al[1]);
            tf_split(Sp0[8 * kcg + tig + 4], ah[2], al[2]);
            tf_split(Sp1[8 * kcg + tig + 4], ah[3], al[3]);
            #pragma unroll
            for (int nt = 0; nt < 16; nt++) {
                const float* vph = SVh + (8 * kcg + tig) * SVS + 8 * nt + g;
                const float* vpl = SVl + (8 * kcg + tig) * SVS + 8 * nt + g;
                uint32_t bh0 = __float_as_uint(vph[0]);
                uint32_t bh1 = __float_as_uint(vph[4 * SVS]);
                uint32_t bl0 = __float_as_uint(vpl[0]);
                uint32_t bl1 = __float_as_uint(vpl[4 * SVS]);
                mma_tf32(o[nt], ah, bh0, bh1);
                mma_tf32(o[nt], ah, bl0, bl1);
                mma_tf32(o[nt], al, bh0, bh1);
            }
        }
    }

    // ---- epilogue: combine halves via smem (reuse SKh), normalize, store ----
    __syncthreads();
    float* OB = SKh;   // 64 x 132
    if (h == 0) {
        #pragma unroll
        for (int nt = 0; nt < 16; nt++) {
            *(float2*)(OB + (wr + g) * SQK + 8 * nt + 2 * tig) =
                make_float2(o[nt][0], o[nt][1]);
            *(float2*)(OB + (wr + 8 + g) * SQK + 8 * nt + 2 * tig) =
                make_float2(o[nt][2], o[nt][3]);
        }
    }
    __syncthreads();
    if (h == 1) {
        float inv0 = 1.0f / l0, inv1 = 1.0f / l1;
        const int r0 = qrow0 + wr + g;
        #pragma unroll
        for (int nt = 0; nt < 16; nt++) {
            int col = 8 * nt + 2 * tig;
            float2 p0 = *(float2*)(OB + (wr + g) * SQK + col);
            float2 p1 = *(float2*)(OB + (wr + 8 + g) * SQK + col);
            *(float2*)(out + (size_t)r0 * DIM + col) =
                make_float2((p0.x + o[nt][0]) * inv0, (p0.y + o[nt][1]) * inv0);
            *(float2*)(out + (size_t)(r0 + 8) * DIM + col) =
                make_float2((p1.x + o[nt][2]) * inv1, (p1.y + o[nt][3]) * inv1);
        }
    }
}

extern "C" void kernel_launch(void* const* d_in, const int* in_sizes, int n_in,
                              void* d_out, int out_size) {
    const float* q = (const float*)d_in[0];
    const float* k = (const float*)d_in[1];
    const float* v = (const float*)d_in[2];
    float* out = (float*)d_out;

    split_kv_kernel<<<NSEQ * DIM / 4 / 256, 256>>>(k, v);

    const int smem_bytes = SMEM_FLOATS * (int)sizeof(float);  // 223,232 B
    cudaFuncSetAttribute(fa_tf32_kernel,
                         cudaFuncAttributeMaxDynamicSharedMemorySize, smem_bytes);

    dim3 grid(NSEQ / BM);   // 128 CTAs
    dim3 block(256);
    fa_tf32_kernel<<<grid, block, smem_bytes>>>(q, out);
}